// round 2
// baseline (speedup 1.0000x reference)
#include <cuda_runtime.h>
#include <cstdint>
#include <math.h>

#define NN 4096
#define TPB 512
#define EPT 8             // NN / TPB
#define DPF 4             // row prefetch depth
#define HSZ 4096
#define HMASK 4095
#define KMAX 64
#define KNEI 5
#define NWARP (TPB / 32)

// device scratch (static; no allocation APIs anywhere)
__device__ int      g_count;
__device__ unsigned g_cells[HSZ];
__device__ float    g_Aarr[HSZ];
__device__ float    g_Barr[HSZ];

static __device__ __forceinline__ unsigned hslot(unsigned key) {
    return (key * 2654435761u) >> 20;   // top 12 bits -> [0,4095]
}

// find slot for key, inserting if absent (safe under concurrency)
static __device__ __forceinline__ int hfind(unsigned* HK, unsigned key) {
    unsigned s = hslot(key);
    while (true) {
        unsigned k = HK[s];
        if (k == key) return (int)s;
        if (k == 0u) {
            unsigned old = atomicCAS(&HK[s], 0u, key);
            if (old == 0u || old == key) return (int)s;
        }
        s = (s + 1u) & HMASK;
    }
}

static __device__ __forceinline__ void cp_row(float* dst, const float* src, int tid) {
    unsigned sa = (unsigned)__cvta_generic_to_shared(dst + tid * EPT);
    const float* g = src + tid * EPT;
#pragma unroll
    for (int j = 0; j < EPT / 4; j++) {
        asm volatile("cp.async.cg.shared.global [%0], [%1], 16;\n"
                     :: "r"(sa + j * 16), "l"(g + j * 4));
    }
}

static __device__ __forceinline__ float4 clamp4(float4 v) {
    v.x = fminf(fmaxf(v.x * 0.999f, -2.0f), 2.0f);
    v.y = fminf(fmaxf(v.y * 0.999f, -2.0f), 2.0f);
    v.z = fminf(fmaxf(v.z * 0.999f, -2.0f), 2.0f);
    v.w = fminf(fmaxf(v.w * 0.999f, -2.0f), 2.0f);
    return v;
}

// merge two sorted-desc 5-lists (with [5]=0 sentinels) -> top5 into L
static __device__ __forceinline__ void merge5(unsigned long long* L, const unsigned long long* R) {
    unsigned long long m[5];
    int i1 = 0, j1 = 0;
#pragma unroll
    for (int k = 0; k < 5; k++) {
        unsigned long long a = L[i1], b = R[j1];
        if (a >= b) { m[k] = a; i1++; } else { m[k] = b; j1++; }
    }
#pragma unroll
    for (int k = 0; k < 5; k++) L[k] = m[k];
}

// ---------------------------------------------------------------------------
// k_main: block 0 = full spark scan (incl. initial state update);
//         blocks 1..G-1 = decay+clip streaming copy W -> out.
// ---------------------------------------------------------------------------
__global__ void __launch_bounds__(TPB, 1)
k_main(const float* __restrict__ W, const float* __restrict__ s_in,
       const float* __restrict__ noise, const float* __restrict__ u_in,
       const int* __restrict__ pos_in, const float* __restrict__ en_in,
       const int* __restrict__ age_in, float* __restrict__ out, int K) {

    if (blockIdx.x != 0) {
        // ---- decay + clip copy, 8-way batched for MLP ----
        const size_t nv = (size_t)NN * NN / 4;
        const float4* __restrict__ src = (const float4*)W;
        float4* __restrict__ dst = (float4*)(out + NN);
        const size_t S = (size_t)(gridDim.x - 1) * TPB;
        size_t i = (size_t)(blockIdx.x - 1) * TPB + threadIdx.x;
        for (; i + 7 * S < nv; i += 8 * S) {
            float4 v0 = src[i];
            float4 v1 = src[i + S];
            float4 v2 = src[i + 2 * S];
            float4 v3 = src[i + 3 * S];
            float4 v4 = src[i + 4 * S];
            float4 v5 = src[i + 5 * S];
            float4 v6 = src[i + 6 * S];
            float4 v7 = src[i + 7 * S];
            dst[i]         = clamp4(v0);
            dst[i + S]     = clamp4(v1);
            dst[i + 2 * S] = clamp4(v2);
            dst[i + 3 * S] = clamp4(v3);
            dst[i + 4 * S] = clamp4(v4);
            dst[i + 5 * S] = clamp4(v5);
            dst[i + 6 * S] = clamp4(v6);
            dst[i + 7 * S] = clamp4(v7);
        }
        for (; i < nv; i += S) dst[i] = clamp4(src[i]);
        return;
    }

    // ================= spark block =================
    extern __shared__ char sm[];
    float*    s_sh = (float*)sm;                      // NN
    float*    bufs = s_sh + NN;                       // DPF * NN
    unsigned* HK   = (unsigned*)(bufs + DPF * NN);    // HSZ
    float*    HA   = (float*)(HK + HSZ);              // HSZ
    float*    HB   = HA + HSZ;                        // HSZ

    __shared__ int   prevs[KMAX];
    __shared__ float en[KMAX];
    __shared__ int   ag[KMAX];
    __shared__ int   poso[KMAX];
    __shared__ float uarr[KMAX];
    __shared__ long long wsum[NWARP];
    __shared__ int   wcnt[NWARP];
    __shared__ unsigned long long wtop[NWARP][KNEI];
    __shared__ int   sh_top[KNEI];
    __shared__ int   sh_cnt;

    const int tid = threadIdx.x, lane = tid & 31, wid = tid >> 5;

    if (tid < K) {
        prevs[tid] = pos_in[tid];
        en[tid]    = en_in[tid];
        ag[tid]    = age_in[tid];
        uarr[tid]  = u_in[tid];
    }
    if (tid == 0) sh_cnt = 0;

    // ---- initial state update: s = sigmoid(W @ (0.95 s) + 0.05 noise) ----
    int any = 0;
    for (int i = tid; i < NN; i += TPB) {
        float v = s_in[i];
        bufs[i] = v * 0.95f;           // scratch (before prefetch)
        any |= (v != 0.0f);
    }
    if (__syncthreads_or(any)) {
        // general (slow, unexercised for zero s): one row per warp
        for (int r = wid; r < NN; r += NWARP) {
            const float* row = W + (size_t)r * NN;
            float acc = 0.0f;
            for (int j = lane; j < NN; j += 32) acc += row[j] * bufs[j];
#pragma unroll
            for (int o = 16; o; o >>= 1) acc += __shfl_xor_sync(~0u, acc, o);
            if (lane == 0) s_sh[r] = 1.0f / (1.0f + expf(-(acc + 0.05f * noise[r])));
        }
    } else {
        for (int i = tid; i < NN; i += TPB)
            s_sh[i] = 1.0f / (1.0f + expf(-0.05f * noise[i]));
    }
    // init affine hash
    for (int i = tid; i < HSZ; i += TPB) { HK[i] = 0u; HA[i] = 1.0f; HB[i] = 0.0f; }
    __syncthreads();
    // force young sparks (input ages)
    if (tid < K && ag[tid] < 5) s_sh[prevs[tid]] = 1.0f;
    __syncthreads();

    // deep prefetch: rows 0..DPF-1, one commit group each
    for (int d = 0; d < DPF; d++) {
        if (d < K) cp_row(bufs + (size_t)d * NN, W + (size_t)prevs[d] * NN, tid);
        asm volatile("cp.async.commit_group;\n");
    }

    for (int it = 0; it < K; it++) {
        float* cur = bufs + (size_t)(it % DPF) * NN;
        const int prev = prevs[it];

        asm volatile("cp.async.wait_group %0;\n" :: "n"(DPF - 1));
        __syncthreads();                                         // b1

        // patch row with affine deltas
#pragma unroll
        for (int k = 0; k < HSZ / TPB; k++) {
            int slot = tid + k * TPB;
            unsigned key = HK[slot];
            if (key) {
                unsigned kk = key - 1u;
                if ((int)(kk >> 12) == prev) {
                    unsigned cc = kk & 4095u;
                    cur[cc] = fmaf(HA[slot], cur[cc], HB[slot]);
                }
            }
        }
        __syncthreads();                                         // b2

        // ---- exact int64 fixed-point inverse-CDF sample ----
        long long lp[EPT];
        long long run = 0;
#pragma unroll
        for (int j = 0; j < EPT; j++) {
            float v = cur[tid * EPT + j];
            float w = fmaxf(v, 0.0f) + 1e-6f;
            long long q = (long long)(w * 1099511627776.0f);     // * 2^40
            run += q;
            lp[j] = run;
        }
        long long inc = run;
#pragma unroll
        for (int o = 1; o < 32; o <<= 1) {
            long long t = __shfl_up_sync(~0u, inc, o);
            if (lane >= o) inc += t;
        }
        if (lane == 31) wsum[wid] = inc;
        __syncthreads();                                         // b3
        long long wbase = 0, total = 0;
#pragma unroll
        for (int w2 = 0; w2 < NWARP; w2++) {
            long long t = wsum[w2];
            total += t;
            if (w2 < wid) wbase += t;
        }
        const long long base = wbase + inc - run;
        const long long target = (long long)((double)uarr[it] * (double)total);
        int c = 0;
#pragma unroll
        for (int j = 0; j < EPT; j++) c += (base + lp[j] <= target);
        c = (int)__reduce_add_sync(~0u, (unsigned)c);
        if (lane == 0) wcnt[wid] = c;
        __syncthreads();                                         // b4
        int count = 0;
#pragma unroll
        for (int w2 = 0; w2 < NWARP; w2++) count += wcnt[w2];
        const int nxt = min(count, NN - 1);

        // ---- edge learning as affine composition: NO base read needed ----
        if (tid == 0) {
            unsigned key = (unsigned)nxt * 4096u + (unsigned)prev + 1u;
            int s2 = hfind(HK, key);
            float sp = s_sh[prev];
            HB[s2] = HB[s2] * 0.95f + sp * 0.05f;
            HA[s2] = HA[s2] * 0.95f;
            if (nxt == prev) cur[prev] = cur[prev] * 0.95f + sp * 0.05f;
        }
        __syncthreads();                                         // b4b

        // ---- per-thread sorted top-5, then warp shuffle-merge ----
        unsigned long long L[6];
#pragma unroll
        for (int k = 0; k < 6; k++) L[k] = 0ull;
#pragma unroll
        for (int j = 0; j < EPT; j++) {
            int idx = tid * EPT + j;
            float v = fmaxf(cur[idx], 0.0f);
            unsigned long long p =
                ((unsigned long long)__float_as_uint(v) << 12) | (unsigned)(4095 - idx);
            if (p > L[4]) {
                int q = 4;
                while (q > 0 && L[q - 1] < p) { L[q] = L[q - 1]; q--; }
                L[q] = p;
            }
        }
#pragma unroll
        for (int off = 1; off < 32; off <<= 1) {
            unsigned long long R[6];
#pragma unroll
            for (int k = 0; k < 5; k++) R[k] = __shfl_xor_sync(~0u, L[k], off);
            R[5] = 0ull;
            merge5(L, R);
        }
        if (lane == 0) {
#pragma unroll
            for (int k = 0; k < 5; k++) wtop[wid][k] = L[k];
        }
        __syncthreads();                                         // b5

        // prefetch row it+DPF into the buffer just freed (cur fully consumed)
        if (it + DPF < K)
            cp_row(bufs + (size_t)(it % DPF) * NN, W + (size_t)prevs[it + DPF] * NN, tid);
        asm volatile("cp.async.commit_group;\n");

        // warp 0 merges the NWARP warp-tops
        if (wid == 0) {
            unsigned long long M[6];
#pragma unroll
            for (int k = 0; k < 6; k++) M[k] = 0ull;
            if (lane < NWARP) {
#pragma unroll
                for (int k = 0; k < 5; k++) M[k] = wtop[lane][k];
            }
#pragma unroll
            for (int off = 1; off < 32; off <<= 1) {
                unsigned long long R[6];
#pragma unroll
                for (int k = 0; k < 5; k++) R[k] = __shfl_xor_sync(~0u, M[k], off);
                R[5] = 0ull;
                merge5(M, R);
            }
            if (lane == 0) {
#pragma unroll
                for (int r = 0; r < KNEI; r++) sh_top[r] = 4095 - (int)(M[r] & 0xFFFull);
            }
        }
        __syncthreads();                                         // b6

        // ---- ripple: 35 independent B-adds on the affine hash ----
        if (tid < 35) {
            int rr, cc; float dv;
            if (tid < 5)       { rr = prev;            cc = sh_top[tid];     dv = 0.01f;  }
            else if (tid < 10) { rr = sh_top[tid - 5]; cc = prev;            dv = 0.005f; }
            else { int i5 = (tid - 10) / 5, j5 = (tid - 10) % 5;
                   rr = sh_top[i5]; cc = sh_top[j5]; dv = 0.003f; }
            int s2 = hfind(HK, (unsigned)rr * 4096u + (unsigned)cc + 1u);
            atomicAdd(&HB[s2], dv);
        }
        // bookkeeping (deposit BEFORE respawn check, as in ref)
        if (tid == 0) {
            float e = en[it] * 0.98f;
            s_sh[nxt] = e;
            int a = ag[it] + 1;
            int po = nxt;
            if (e < 0.05f) { po = it; e = 1.0f; a = 0; }
            poso[it] = po; en[it] = e; ag[it] = a;
        }
        // next iteration's b1 orders ripple/bookkeeping writes
    }
    __syncthreads();

    // ---- outputs ----
    for (int i = tid; i < NN; i += TPB) out[i] = s_sh[i];
    const size_t OFF = (size_t)NN + (size_t)NN * NN;
    if (tid < K) {
        out[OFF + tid]         = (float)poso[tid];
        out[OFF + K + tid]     = en[tid];
        out[OFF + 2 * K + tid] = (float)ag[tid];
    }
    // dump affine edits for the fixup kernel
#pragma unroll
    for (int k = 0; k < HSZ / TPB; k++) {
        int slot = tid + k * TPB;
        unsigned key = HK[slot];
        if (key) {
            int i = atomicAdd(&sh_cnt, 1);
            g_cells[i] = key - 1u;
            g_Aarr[i]  = HA[slot];
            g_Barr[i]  = HB[slot];
        }
    }
    __syncthreads();
    if (tid == 0) g_count = sh_cnt;
}

// ---------------------------------------------------------------------------
// k_fix: overwrite spark-edited W cells with clip((A*W + B) * 0.999)
// ---------------------------------------------------------------------------
__global__ void k_fix(const float* __restrict__ W, float* __restrict__ out) {
    int n = g_count;
    for (int i = blockIdx.x * blockDim.x + threadIdx.x; i < n;
         i += gridDim.x * blockDim.x) {
        unsigned cell = g_cells[i];
        float v = fmaf(g_Aarr[i], W[cell], g_Barr[i]) * 0.999f;
        v = fminf(fmaxf(v, -2.0f), 2.0f);
        out[(size_t)NN + cell] = v;
    }
}

extern "C" void kernel_launch(void* const* d_in, const int* in_sizes, int n_in,
                              void* d_out, int out_size) {
    const float* W     = (const float*)d_in[0];
    const float* s     = (const float*)d_in[1];
    const float* noise = (const float*)d_in[2];
    const float* en    = (const float*)d_in[3];
    const float* u     = (const float*)d_in[4];
    const int*   pos   = (const int*)d_in[5];
    const int*   age   = (const int*)d_in[6];
    float* out = (float*)d_out;
    int K = in_sizes[3];
    if (K > KMAX) K = KMAX;

    const int smem = (NN + DPF * NN) * 4 + HSZ * 4 * 3;   // 128 KB
    cudaFuncSetAttribute(k_main, cudaFuncAttributeMaxDynamicSharedMemorySize, smem);

    k_main<<<148, TPB, smem>>>(W, s, noise, u, pos, en, age, out, K);
    k_fix<<<16, 256>>>(W, out);
}

// round 3
// speedup vs baseline: 1.5731x; 1.5731x over previous
#include <cuda_runtime.h>
#include <cstdint>
#include <math.h>

#define NN 4096
#define TPB 256
#define EPT 16            // NN / TPB
#define DPF 3             // row prefetch depth
#define HSZ 4096
#define HMASK 4095
#define KMAX 64
#define KNEI 5
#define NWARP (TPB / 32)

// device scratch (static; no allocation APIs anywhere)
__device__ int      g_count;
__device__ unsigned g_cells[HSZ];
__device__ float    g_Aarr[HSZ];
__device__ float    g_Barr[HSZ];

static __device__ __forceinline__ unsigned hslot(unsigned key) {
    return (key * 2654435761u) >> 20;   // top 12 bits -> [0,4095]
}

// find slot for key, inserting if absent (safe under concurrency)
static __device__ __forceinline__ int hfind(unsigned* HK, unsigned key) {
    unsigned s = hslot(key);
    while (true) {
        unsigned k = HK[s];
        if (k == key) return (int)s;
        if (k == 0u) {
            unsigned old = atomicCAS(&HK[s], 0u, key);
            if (old == 0u || old == key) return (int)s;
        }
        s = (s + 1u) & HMASK;
    }
}

static __device__ __forceinline__ void cp_row(float* dst, const float* src, int tid) {
    unsigned sa = (unsigned)__cvta_generic_to_shared(dst + tid * EPT);
    const float* g = src + tid * EPT;
#pragma unroll
    for (int j = 0; j < EPT / 4; j++) {
        asm volatile("cp.async.cg.shared.global [%0], [%1], 16;\n"
                     :: "r"(sa + j * 16), "l"(g + j * 4));
    }
}

static __device__ __forceinline__ float4 clamp4(float4 v) {
    v.x = fminf(fmaxf(v.x * 0.999f, -2.0f), 2.0f);
    v.y = fminf(fmaxf(v.y * 0.999f, -2.0f), 2.0f);
    v.z = fminf(fmaxf(v.z * 0.999f, -2.0f), 2.0f);
    v.w = fminf(fmaxf(v.w * 0.999f, -2.0f), 2.0f);
    return v;
}

// branchless compare-swap: a takes max, b takes min (named regs only -> no spills)
static __device__ __forceinline__ void cswap(unsigned long long& a, unsigned long long& b) {
    unsigned long long mx = (a > b) ? a : b;
    unsigned long long mn = (a > b) ? b : a;
    a = mx; b = mn;
}

// full descending sort of 5 named regs (bubble network, 10 comparators, spill-free)
#define SORT5(t0, t1, t2, t3, t4)                          \
    do {                                                   \
        cswap(t0, t1); cswap(t1, t2); cswap(t2, t3); cswap(t3, t4); \
        cswap(t0, t1); cswap(t1, t2); cswap(t2, t3);       \
        cswap(t0, t1); cswap(t1, t2);                      \
        cswap(t0, t1);                                     \
    } while (0)

// merge my sorted-desc top5 with xor-lane's: bitonic half-cleaner + cleanup sort
#define MERGE_STEP(off)                                                   \
    do {                                                                  \
        unsigned long long o0 = __shfl_xor_sync(0xffffffffu, t0, (off)); \
        unsigned long long o1 = __shfl_xor_sync(0xffffffffu, t1, (off)); \
        unsigned long long o2 = __shfl_xor_sync(0xffffffffu, t2, (off)); \
        unsigned long long o3 = __shfl_xor_sync(0xffffffffu, t3, (off)); \
        unsigned long long o4 = __shfl_xor_sync(0xffffffffu, t4, (off)); \
        t0 = (t0 > o4) ? t0 : o4;                                        \
        t1 = (t1 > o3) ? t1 : o3;                                        \
        t2 = (t2 > o2) ? t2 : o2;                                        \
        t3 = (t3 > o1) ? t3 : o1;                                        \
        t4 = (t4 > o0) ? t4 : o0;                                        \
        SORT5(t0, t1, t2, t3, t4);                                       \
    } while (0)

// ---------------------------------------------------------------------------
// k_main: block 0 = state update + sequential spark scan (affine delta hash);
//         blocks 1..G-1 = decay+clip streaming copy W -> out.
// ---------------------------------------------------------------------------
__global__ void __launch_bounds__(TPB, 1)
k_main(const float* __restrict__ W, const float* __restrict__ s_in,
       const float* __restrict__ noise, const float* __restrict__ u_in,
       const int* __restrict__ pos_in, const float* __restrict__ en_in,
       const int* __restrict__ age_in, float* __restrict__ out, int K) {

    if (blockIdx.x != 0) {
        // ---- decay + clip copy, 8-way explicit load batching for MLP ----
        const size_t nv = (size_t)NN * NN / 4;
        const float4* __restrict__ src = (const float4*)W;
        float4* __restrict__ dst = (float4*)(out + NN);
        const size_t S = (size_t)(gridDim.x - 1) * TPB;
        size_t i = (size_t)(blockIdx.x - 1) * TPB + threadIdx.x;
        for (; i + 7 * S < nv; i += 8 * S) {
            float4 v0 = src[i];
            float4 v1 = src[i + S];
            float4 v2 = src[i + 2 * S];
            float4 v3 = src[i + 3 * S];
            float4 v4 = src[i + 4 * S];
            float4 v5 = src[i + 5 * S];
            float4 v6 = src[i + 6 * S];
            float4 v7 = src[i + 7 * S];
            dst[i]         = clamp4(v0);
            dst[i + S]     = clamp4(v1);
            dst[i + 2 * S] = clamp4(v2);
            dst[i + 3 * S] = clamp4(v3);
            dst[i + 4 * S] = clamp4(v4);
            dst[i + 5 * S] = clamp4(v5);
            dst[i + 6 * S] = clamp4(v6);
            dst[i + 7 * S] = clamp4(v7);
        }
        for (; i < nv; i += S) dst[i] = clamp4(src[i]);
        return;
    }

    // ================= spark block =================
    extern __shared__ char sm[];
    float*    s_sh = (float*)sm;                      // NN
    float*    bufs = s_sh + NN;                       // DPF * NN
    unsigned* HK   = (unsigned*)(bufs + DPF * NN);    // HSZ
    float*    HA   = (float*)(HK + HSZ);              // HSZ
    float*    HB   = HA + HSZ;                        // HSZ

    __shared__ int   prevs[KMAX];
    __shared__ float en[KMAX];
    __shared__ int   ag[KMAX];
    __shared__ int   poso[KMAX];
    __shared__ float uarr[KMAX];
    __shared__ long long wsum[NWARP];
    __shared__ int   wcnt[NWARP];
    __shared__ unsigned long long wtop[NWARP][KNEI];
    __shared__ int   sh_top[KNEI];
    __shared__ int   sh_cnt;

    const int tid = threadIdx.x, lane = tid & 31, wid = tid >> 5;

    if (tid < K) {
        prevs[tid] = pos_in[tid];
        en[tid]    = en_in[tid];
        ag[tid]    = age_in[tid];
        uarr[tid]  = u_in[tid];
    }
    if (tid == 0) sh_cnt = 0;

    // ---- initial state: s = sigmoid(W @ (0.95 s) + 0.05 noise) ----
    int any = 0;
    for (int i = tid; i < NN; i += TPB) {
        float v = s_in[i];
        bufs[i] = v * 0.95f;           // scratch (before prefetch)
        any |= (v != 0.0f);
    }
    if (__syncthreads_or(any)) {
        // general path (unexercised for zero s): one row per warp
        for (int r = wid; r < NN; r += NWARP) {
            const float* row = W + (size_t)r * NN;
            float acc = 0.0f;
            for (int j = lane; j < NN; j += 32) acc += row[j] * bufs[j];
#pragma unroll
            for (int o = 16; o; o >>= 1) acc += __shfl_xor_sync(~0u, acc, o);
            if (lane == 0) s_sh[r] = 1.0f / (1.0f + expf(-(acc + 0.05f * noise[r])));
        }
    } else {
        for (int i = tid; i < NN; i += TPB)
            s_sh[i] = 1.0f / (1.0f + expf(-0.05f * noise[i]));
    }
    // init affine hash
    for (int i = tid; i < HSZ; i += TPB) { HK[i] = 0u; HA[i] = 1.0f; HB[i] = 0.0f; }
    __syncthreads();
    // force young sparks (input ages)
    if (tid < K && ag[tid] < 5) s_sh[prevs[tid]] = 1.0f;
    __syncthreads();

    // deep prefetch: rows 0..DPF-1, one commit group each
    for (int d = 0; d < DPF; d++) {
        if (d < K) cp_row(bufs + (size_t)d * NN, W + (size_t)prevs[d] * NN, tid);
        asm volatile("cp.async.commit_group;\n");
    }

    for (int it = 0; it < K; it++) {
        float* cur = bufs + (size_t)(it % DPF) * NN;
        const int prev = prevs[it];

        asm volatile("cp.async.wait_group %0;\n" :: "n"(DPF - 1));
        __syncthreads();                                         // b1

        // patch row with affine deltas
#pragma unroll
        for (int k = 0; k < HSZ / TPB; k++) {
            int slot = tid + k * TPB;
            unsigned key = HK[slot];
            if (key) {
                unsigned kk = key - 1u;
                if ((int)(kk >> 12) == prev) {
                    unsigned cc = kk & 4095u;
                    cur[cc] = fmaf(HA[slot], cur[cc], HB[slot]);
                }
            }
        }
        __syncthreads();                                         // b2

        // ---- exact int64 fixed-point inverse-CDF sample ----
        const float4* crow = (const float4*)(cur + tid * EPT);
        long long lp[EPT];
        long long run = 0;
#pragma unroll
        for (int j4 = 0; j4 < EPT / 4; j4++) {
            float4 f = crow[j4];
            run += (long long)((fmaxf(f.x, 0.0f) + 1e-6f) * 1099511627776.0f); lp[j4 * 4 + 0] = run;
            run += (long long)((fmaxf(f.y, 0.0f) + 1e-6f) * 1099511627776.0f); lp[j4 * 4 + 1] = run;
            run += (long long)((fmaxf(f.z, 0.0f) + 1e-6f) * 1099511627776.0f); lp[j4 * 4 + 2] = run;
            run += (long long)((fmaxf(f.w, 0.0f) + 1e-6f) * 1099511627776.0f); lp[j4 * 4 + 3] = run;
        }
        long long inc = run;
#pragma unroll
        for (int o = 1; o < 32; o <<= 1) {
            long long t = __shfl_up_sync(~0u, inc, o);
            if (lane >= o) inc += t;
        }
        if (lane == 31) wsum[wid] = inc;
        __syncthreads();                                         // b3
        long long wbase = 0, total = 0;
#pragma unroll
        for (int w2 = 0; w2 < NWARP; w2++) {
            long long t = wsum[w2];
            total += t;
            if (w2 < wid) wbase += t;
        }
        const long long base = wbase + inc - run;
        const long long target = (long long)((double)uarr[it] * (double)total);
        int c = 0;
#pragma unroll
        for (int j = 0; j < EPT; j++) c += (base + lp[j] <= target);
        c = (int)__reduce_add_sync(~0u, (unsigned)c);
        if (lane == 0) wcnt[wid] = c;
        __syncthreads();                                         // b4
        int count = 0;
#pragma unroll
        for (int w2 = 0; w2 < NWARP; w2++) count += wcnt[w2];
        const int nxt = min(count, NN - 1);

        // ---- edge learning: affine composition (no base read, no barrier) ----
        if (tid == 0) {
            unsigned key = (unsigned)nxt * 4096u + (unsigned)prev + 1u;
            int s2 = hfind(HK, key);
            float sp = s_sh[prev];
            HB[s2] = HB[s2] * 0.95f + sp * 0.05f;
            HA[s2] = HA[s2] * 0.95f;
        }
        // owner thread applies the (rare) same-row fix locally; only it reads that cell
        if (nxt == prev && tid == (prev >> 4)) {
            cur[prev] = cur[prev] * 0.95f + s_sh[prev] * 0.05f;
        }

        // ---- per-thread top-5 (named regs, branchless insert) ----
        unsigned long long t0 = 0, t1 = 0, t2 = 0, t3 = 0, t4 = 0;
#pragma unroll
        for (int j4 = 0; j4 < EPT / 4; j4++) {
            float4 f = crow[j4];
#pragma unroll
            for (int e = 0; e < 4; e++) {
                float v = (e == 0) ? f.x : (e == 1) ? f.y : (e == 2) ? f.z : f.w;
                int idx = tid * EPT + j4 * 4 + e;
                unsigned long long p =
                    ((unsigned long long)__float_as_uint(fmaxf(v, 0.0f)) << 12) |
                    (unsigned)(4095 - idx);
                t4 = (t4 > p) ? t4 : p;
                cswap(t3, t4); cswap(t2, t3); cswap(t1, t2); cswap(t0, t1);
            }
        }
        // warp merge (spill-free shuffle network)
        MERGE_STEP(1); MERGE_STEP(2); MERGE_STEP(4); MERGE_STEP(8); MERGE_STEP(16);
        if (lane == 0) {
            wtop[wid][0] = t0; wtop[wid][1] = t1; wtop[wid][2] = t2;
            wtop[wid][3] = t3; wtop[wid][4] = t4;
        }
        __syncthreads();                                         // b5

        // prefetch row it+DPF into the buffer just freed (all cur reads done)
        if (it + DPF < K)
            cp_row(bufs + (size_t)(it % DPF) * NN, W + (size_t)prevs[it + DPF] * NN, tid);
        asm volatile("cp.async.commit_group;\n");

        // warp 0 merges the NWARP warp-tops (lanes >= NWARP hold zeros)
        if (wid == 0) {
            t0 = t1 = t2 = t3 = t4 = 0ull;
            if (lane < NWARP) {
                t0 = wtop[lane][0]; t1 = wtop[lane][1]; t2 = wtop[lane][2];
                t3 = wtop[lane][3]; t4 = wtop[lane][4];
            }
            MERGE_STEP(1); MERGE_STEP(2); MERGE_STEP(4);
            if (lane == 0) {
                sh_top[0] = 4095 - (int)(t0 & 0xFFFull);
                sh_top[1] = 4095 - (int)(t1 & 0xFFFull);
                sh_top[2] = 4095 - (int)(t2 & 0xFFFull);
                sh_top[3] = 4095 - (int)(t3 & 0xFFFull);
                sh_top[4] = 4095 - (int)(t4 & 0xFFFull);
            }
        }
        __syncthreads();                                         // b6

        // ---- ripple: 35 independent B-adds on the affine hash ----
        if (tid < 35) {
            int rr, cc; float dv;
            if (tid < 5)       { rr = prev;            cc = sh_top[tid];     dv = 0.01f;  }
            else if (tid < 10) { rr = sh_top[tid - 5]; cc = prev;            dv = 0.005f; }
            else { int i5 = (tid - 10) / 5, j5 = (tid - 10) % 5;
                   rr = sh_top[i5]; cc = sh_top[j5]; dv = 0.003f; }
            int s2 = hfind(HK, (unsigned)rr * 4096u + (unsigned)cc + 1u);
            atomicAdd(&HB[s2], dv);
        }
        // bookkeeping (deposit BEFORE respawn check, as in ref)
        if (tid == 0) {
            float e = en[it] * 0.98f;
            s_sh[nxt] = e;
            int a = ag[it] + 1;
            int po = nxt;
            if (e < 0.05f) { po = it; e = 1.0f; a = 0; }
            poso[it] = po; en[it] = e; ag[it] = a;
        }
        // next iteration's b1 orders ripple/bookkeeping writes before reads
    }
    __syncthreads();

    // ---- outputs ----
    for (int i = tid; i < NN; i += TPB) out[i] = s_sh[i];
    const size_t OFF = (size_t)NN + (size_t)NN * NN;
    if (tid < K) {
        out[OFF + tid]         = (float)poso[tid];
        out[OFF + K + tid]     = en[tid];
        out[OFF + 2 * K + tid] = (float)ag[tid];
    }
    // dump affine edits for the fixup kernel
#pragma unroll
    for (int k = 0; k < HSZ / TPB; k++) {
        int slot = tid + k * TPB;
        unsigned key = HK[slot];
        if (key) {
            int i = atomicAdd(&sh_cnt, 1);
            g_cells[i] = key - 1u;
            g_Aarr[i]  = HA[slot];
            g_Barr[i]  = HB[slot];
        }
    }
    __syncthreads();
    if (tid == 0) g_count = sh_cnt;
}

// ---------------------------------------------------------------------------
// k_fix: overwrite spark-edited W cells with clip((A*W + B) * 0.999)
// ---------------------------------------------------------------------------
__global__ void k_fix(const float* __restrict__ W, float* __restrict__ out) {
    int n = g_count;
    for (int i = blockIdx.x * blockDim.x + threadIdx.x; i < n;
         i += gridDim.x * blockDim.x) {
        unsigned cell = g_cells[i];
        float v = fmaf(g_Aarr[i], W[cell], g_Barr[i]) * 0.999f;
        v = fminf(fmaxf(v, -2.0f), 2.0f);
        out[(size_t)NN + cell] = v;
    }
}

extern "C" void kernel_launch(void* const* d_in, const int* in_sizes, int n_in,
                              void* d_out, int out_size) {
    const float* W     = (const float*)d_in[0];
    const float* s     = (const float*)d_in[1];
    const float* noise = (const float*)d_in[2];
    const float* en    = (const float*)d_in[3];
    const float* u     = (const float*)d_in[4];
    const int*   pos   = (const int*)d_in[5];
    const int*   age   = (const int*)d_in[6];
    float* out = (float*)d_out;
    int K = in_sizes[3];
    if (K > KMAX) K = KMAX;

    const int smem = (NN + DPF * NN) * 4 + HSZ * 4 * 3;   // 112 KB
    cudaFuncSetAttribute(k_main, cudaFuncAttributeMaxDynamicSharedMemorySize, smem);

    k_main<<<148, TPB, smem>>>(W, s, noise, u, pos, en, age, out, K);
    k_fix<<<16, 256>>>(W, out);
}